// round 8
// baseline (speedup 1.0000x reference)
#include <cuda_runtime.h>
#include <cuda_fp16.h>

// Problem constants
#define B_   4
#define IC   16      // inDim
#define S_   4096    // nSeq
#define O_   64      // outDim
#define W_   64      // nWin
#define OH   16      // outputs per CTA
#define TT   256     // time-tile per CTA
#define ECH  8       // events per chunk (two 4-event passes)

// Shared memory (bytes):
//  wsm : fp16 staging [row=i*16+wq][16 uint2 swizzled] = 32768 B  (init only)
//  trf : fp16 [row=e*64+w][24 halves, 16 used]         = 24576 B  (ALIASES wsm)
//  xs  : fp32 2 x 128                                  at 32768
//  src : 2 x 8 ints                                    at 33792
#define XS_OFF_B   32768
#define SRC_OFF_B  (XS_OFF_B + 2*128*4)
#define SMEM_BYTES (SRC_OFF_B + 64)      // ~33.9 KB -> 3 CTAs/SM

__device__ __forceinline__ unsigned long long ffma2(unsigned long long a,
                                                    unsigned long long b,
                                                    unsigned long long c) {
    unsigned long long d;
    asm("fma.rn.f32x2 %0, %1, %2, %3;" : "=l"(d) : "l"(a), "l"(b), "l"(c));
    return d;
}
__device__ __forceinline__ unsigned long long add2(unsigned long long a,
                                                   unsigned long long b) {
    unsigned long long d;
    asm("add.rn.f32x2 %0, %1, %2;" : "=l"(d) : "l"(a), "l"(b));
    return d;
}
__device__ __forceinline__ unsigned long long pack2(float lo, float hi) {
    unsigned long long d;
    asm("mov.b64 %0, {%1, %2};" : "=l"(d) : "f"(lo), "f"(hi));
    return d;
}
__device__ __forceinline__ void unpack2(unsigned long long v, float& lo, float& hi) {
    asm("mov.b64 {%0, %1}, %2;" : "=f"(lo), "=f"(hi) : "l"(v));
}

__global__ __launch_bounds__(256, 3)
void astrf_kernel(const float* __restrict__ x, const float* __restrict__ wt,
                  const float* __restrict__ bias, const int* __restrict__ srcIdx,
                  float* __restrict__ out, int T)
{
    extern __shared__ char smemc[];
    uint2*  wsm2  = (uint2*)smemc;                 // staging view
    __half* trf   = (__half*)smemc;                // loop view (aliases wsm)
    float*  xs    = (float*)(smemc + XS_OFF_B);
    int*    srcsm = (int*)(smemc + SRC_OFF_B);

    const int tid   = threadIdx.x;
    const int b     = blockIdx.z;
    const int oBase = blockIdx.y * OH;
    const int t0    = blockIdx.x * TT;

    // ---- Stage weights: gmem f32 -> smem f16, XOR-swizzled (coalesced gmem).
    {
        const int lane = tid & 31;
        #pragma unroll
        for (int r = 0; r < 2; r++) {
            const int o = (tid >> 5) + r * 8;     // 0..15
            const float4* gw = (const float4*)(wt + (size_t)(oBase + o) * (IC * W_));
            #pragma unroll
            for (int u = 0; u < 8; u++) {
                int row = lane + u * 32;                   // 0..255 = i*16 + wq
                float4 v = gw[row];
                __half2 h01 = __floats2half2_rn(v.x, v.y);
                __half2 h23 = __floats2half2_rn(v.z, v.w);
                uint2 hv;
                hv.x = *(unsigned*)&h01; hv.y = *(unsigned*)&h23;
                wsm2[row * 16 + (o ^ (row & 15))] = hv;
            }
        }
    }

    // ---- Per-thread binary search for event window [t0-(W-1), t0+TT)
    int sLo, sHi;
    {
        const int* sp = srcIdx + b * S_;
        int lo = 0, hi = S_, tgt = t0 - (W_ - 1);
        while (lo < hi) { int m = (lo + hi) >> 1; if (sp[m] < tgt) lo = m + 1; else hi = m; }
        sLo = lo;
        lo = 0; hi = S_; tgt = t0 + TT;
        while (lo < hi) { int m = (lo + hi) >> 1; if (sp[m] < tgt) lo = m + 1; else hi = m; }
        sHi = lo;
    }

    // Thread roles
    const int oA  = tid & 15;            // Phase A: output lane
    const int wqA = tid >> 4;            // Phase A: w-quad (0..15)

    __syncthreads();   // wsm staged

    // ---- Pull this thread's weight slice into registers (conflict-free LDS.64)
    uint2 wreg[IC];
    #pragma unroll
    for (int i = 0; i < IC; i++)
        wreg[i] = wsm2[(i * 16 + wqA) * 16 + (oA ^ wqA)];

    // ---- x/src staging (regions do NOT alias wsm)
    auto stage = [&](int c0, int buf) {
        if (tid < 128) {
            int i = tid >> 3, e = tid & 7;
            float v = (c0 + e < sHi) ? x[(size_t)(b * IC + i) * S_ + c0 + e] : 0.f;
            xs[buf * 128 + i * 8 + e] = v;
        } else if (tid < 136) {
            int k = tid - 128;
            srcsm[buf * 8 + k] = (c0 + k < sHi) ? srcIdx[b * S_ + c0 + k] : (1 << 29);
        }
    };
    stage(sLo, 0);

    // Persistent accumulators: 16 outputs as 8 f32x2
    unsigned long long acc2[8];
    #pragma unroll
    for (int k = 0; k < 8; k++) acc2[k] = 0ull;

    __syncthreads();   // reg-loads done (trf may now overwrite wsm), xs ready

    int cur = 0;
    for (int c0 = sLo; c0 < sHi; c0 += ECH) {
        // ---- Phase A: two 4-event passes over register-resident weights.
        // a2[4][2] keeps the live accumulator file small (occ 3).
        const float* xb = xs + cur * 128;
        #pragma unroll
        for (int pass = 0; pass < 2; pass++) {
            unsigned long long a2[4][2];
            #pragma unroll
            for (int le = 0; le < 4; le++) { a2[le][0] = 0ull; a2[le][1] = 0ull; }

            #pragma unroll
            for (int i = 0; i < IC; i++) {
                float2 f01 = __half22float2(*(__half2*)&wreg[i].x);
                float2 f23 = __half22float2(*(__half2*)&wreg[i].y);
                unsigned long long w01 = pack2(f01.x, f01.y);
                unsigned long long w23 = pack2(f23.x, f23.y);
                float4 xv = *(const float4*)(xb + i * 8 + pass * 4); // bcast LDS.128
                unsigned long long x0 = pack2(xv.x, xv.x);
                unsigned long long x1 = pack2(xv.y, xv.y);
                unsigned long long x2 = pack2(xv.z, xv.z);
                unsigned long long x3 = pack2(xv.w, xv.w);
                a2[0][0] = ffma2(w01, x0, a2[0][0]);
                a2[0][1] = ffma2(w23, x0, a2[0][1]);
                a2[1][0] = ffma2(w01, x1, a2[1][0]);
                a2[1][1] = ffma2(w23, x1, a2[1][1]);
                a2[2][0] = ffma2(w01, x2, a2[2][0]);
                a2[2][1] = ffma2(w23, x2, a2[2][1]);
                a2[3][0] = ffma2(w01, x3, a2[3][0]);
                a2[3][1] = ffma2(w23, x3, a2[3][1]);
            }
            // store trf fp16, rows (e*64 + w) stride 24 halves, col oA
            #pragma unroll
            for (int le = 0; le < 4; le++) {
                int e = pass * 4 + le;
                float f0, f1, f2, f3;
                unpack2(a2[le][0], f0, f1);
                unpack2(a2[le][1], f2, f3);
                __half* p = trf + (e * 64 + wqA * 4) * 24 + oA;
                p[0]  = __float2half_rn(f0);
                p[24] = __float2half_rn(f1);
                p[48] = __float2half_rn(f2);
                p[72] = __float2half_rn(f3);
            }
        }
        __syncthreads();   // trf ready; xs[cur] fully consumed

        // ---- Stage next chunk into the other buffer (overlaps Phase B)
        if (c0 + ECH < sHi) stage(c0 + ECH, cur ^ 1);

        // ---- Phase B: overlap-add; 2 conflict-free LDS.128 per event hit
        {
            const int t = t0 + tid;
            const int* sp = srcsm + cur * 8;
            #pragma unroll
            for (int e = 0; e < ECH; e++) {
                int w = t - sp[e];
                if ((unsigned)w < (unsigned)W_) {
                    const __half* rp = trf + (e * 64 + w) * 24;
                    uint4 v0 = *(const uint4*)rp;          // halves o0..o7
                    uint4 v1 = *(const uint4*)(rp + 8);    // halves o8..o15
                    float2 g0 = __half22float2(*(__half2*)&v0.x);
                    float2 g1 = __half22float2(*(__half2*)&v0.y);
                    float2 g2 = __half22float2(*(__half2*)&v0.z);
                    float2 g3 = __half22float2(*(__half2*)&v0.w);
                    float2 g4 = __half22float2(*(__half2*)&v1.x);
                    float2 g5 = __half22float2(*(__half2*)&v1.y);
                    float2 g6 = __half22float2(*(__half2*)&v1.z);
                    float2 g7 = __half22float2(*(__half2*)&v1.w);
                    acc2[0] = add2(acc2[0], pack2(g0.x, g0.y));
                    acc2[1] = add2(acc2[1], pack2(g1.x, g1.y));
                    acc2[2] = add2(acc2[2], pack2(g2.x, g2.y));
                    acc2[3] = add2(acc2[3], pack2(g3.x, g3.y));
                    acc2[4] = add2(acc2[4], pack2(g4.x, g4.y));
                    acc2[5] = add2(acc2[5], pack2(g5.x, g5.y));
                    acc2[6] = add2(acc2[6], pack2(g6.x, g6.y));
                    acc2[7] = add2(acc2[7], pack2(g7.x, g7.y));
                }
            }
        }
        __syncthreads();   // Phase B done reading trf; next x staged
        cur ^= 1;
    }

    // ---- Epilogue: bias + direct coalesced store (lanes = consecutive t)
    {
        const int t = t0 + tid;
        #pragma unroll
        for (int j = 0; j < 8; j++) {
            float f0, f1;
            unpack2(acc2[j], f0, f1);
            int o0 = oBase + 2 * j;
            out[(size_t)(b * O_ + o0) * T + t]     = f0 + __ldg(bias + o0);
            out[(size_t)(b * O_ + o0 + 1) * T + t] = f1 + __ldg(bias + o0 + 1);
        }
    }
}

extern "C" void kernel_launch(void* const* d_in, const int* in_sizes, int n_in,
                              void* d_out, int out_size) {
    (void)in_sizes; (void)n_in;
    const float* x    = (const float*)d_in[0];
    const float* wt   = (const float*)d_in[1];
    const float* bias = (const float*)d_in[2];
    const int*   src  = (const int*)d_in[3];
    float* out = (float*)d_out;

    int T = out_size / (B_ * O_);   // 32768
    cudaFuncSetAttribute(astrf_kernel, cudaFuncAttributeMaxDynamicSharedMemorySize, SMEM_BYTES);
    dim3 grid(T / TT, O_ / OH, B_);
    astrf_kernel<<<grid, 256, SMEM_BYTES>>>(x, wt, bias, src, out, T);
}

// round 11
// speedup vs baseline: 1.3111x; 1.3111x over previous
#include <cuda_runtime.h>
#include <cuda_fp16.h>

// Problem constants
#define B_   4
#define IC   16      // inDim
#define S_   4096    // nSeq
#define O_   64      // outDim
#define W_   64      // nWin
#define OH   16      // outputs per CTA
#define TT   256     // time-tile per CTA
#define ECH  8       // events per chunk

// Shared memory (bytes):
//  wsm : fp16 [row=i*16+wq][16 uint2 swizzled] = 32768 B  (live whole kernel)
//  trf : fp16 [row=e*64+w][24 halves, 16 used] = 24576 B  at 32768
//  xs  : fp32 2 x 128                          at 57344
//  src : 2 x 8 ints                            at 58368
#define TRF_OFF_B  32768
#define XS_OFF_B   (TRF_OFF_B + 24576)          // 57344
#define SRC_OFF_B  (XS_OFF_B + 2*128*4)         // 58368
#define SMEM_BYTES (SRC_OFF_B + 64)             // ~58.4 KB -> 3 CTAs/SM

__device__ __forceinline__ unsigned long long ffma2(unsigned long long a,
                                                    unsigned long long b,
                                                    unsigned long long c) {
    unsigned long long d;
    asm("fma.rn.f32x2 %0, %1, %2, %3;" : "=l"(d) : "l"(a), "l"(b), "l"(c));
    return d;
}
__device__ __forceinline__ unsigned long long add2(unsigned long long a,
                                                   unsigned long long b) {
    unsigned long long d;
    asm("add.rn.f32x2 %0, %1, %2;" : "=l"(d) : "l"(a), "l"(b));
    return d;
}
__device__ __forceinline__ unsigned long long pack2(float lo, float hi) {
    unsigned long long d;
    asm("mov.b64 %0, {%1, %2};" : "=l"(d) : "f"(lo), "f"(hi));
    return d;
}
__device__ __forceinline__ void unpack2(unsigned long long v, float& lo, float& hi) {
    asm("mov.b64 {%0, %1}, %2;" : "=f"(lo), "=f"(hi) : "l"(v));
}

__global__ __launch_bounds__(256, 3)
void astrf_kernel(const float* __restrict__ x, const float* __restrict__ wt,
                  const float* __restrict__ bias, const int* __restrict__ srcIdx,
                  float* __restrict__ out, int T)
{
    extern __shared__ char smemc[];
    uint2*  wsm2  = (uint2*)smemc;                     // weights (live)
    __half* trf   = (__half*)(smemc + TRF_OFF_B);
    float*  xs    = (float*)(smemc + XS_OFF_B);
    int*    srcsm = (int*)(smemc + SRC_OFF_B);

    const int tid   = threadIdx.x;
    const int b     = blockIdx.z;
    const int oBase = blockIdx.y * OH;
    const int t0    = blockIdx.x * TT;

    // ---- Stage weights: gmem f32 -> smem f16, XOR-swizzled (coalesced gmem).
    {
        const int lane = tid & 31;
        #pragma unroll
        for (int r = 0; r < 2; r++) {
            const int o = (tid >> 5) + r * 8;     // 0..15
            const float4* gw = (const float4*)(wt + (size_t)(oBase + o) * (IC * W_));
            #pragma unroll
            for (int u = 0; u < 8; u++) {
                int row = lane + u * 32;                   // 0..255 = i*16 + wq
                float4 v = gw[row];
                __half2 h01 = __floats2half2_rn(v.x, v.y);
                __half2 h23 = __floats2half2_rn(v.z, v.w);
                uint2 hv;
                hv.x = *(unsigned*)&h01; hv.y = *(unsigned*)&h23;
                wsm2[row * 16 + (o ^ (row & 15))] = hv;
            }
        }
    }

    // ---- Per-thread binary search for event window [t0-(W-1), t0+TT)
    int sLo, sHi;
    {
        const int* sp = srcIdx + b * S_;
        int lo = 0, hi = S_, tgt = t0 - (W_ - 1);
        while (lo < hi) { int m = (lo + hi) >> 1; if (sp[m] < tgt) lo = m + 1; else hi = m; }
        sLo = lo;
        lo = 0; hi = S_; tgt = t0 + TT;
        while (lo < hi) { int m = (lo + hi) >> 1; if (sp[m] < tgt) lo = m + 1; else hi = m; }
        sHi = lo;
    }

    // Thread roles
    const int oA  = tid & 15;            // Phase A: output lane
    const int wqA = tid >> 4;            // Phase A: w-quad (0..15)

    // Phase-A weight pointer (swizzle term == wqA, constant per thread)
    const uint2* wA = wsm2 + wqA * 16 + (oA ^ wqA);

    // Persistent accumulators: 16 outputs as 8 f32x2
    unsigned long long acc2[8];
    #pragma unroll
    for (int k = 0; k < 8; k++) acc2[k] = 0ull;

    // ---- x/src staging
    auto stage = [&](int c0, int buf) {
        if (tid < 128) {
            int i = tid >> 3, e = tid & 7;
            float v = (c0 + e < sHi) ? x[(size_t)(b * IC + i) * S_ + c0 + e] : 0.f;
            xs[buf * 128 + i * 8 + e] = v;
        } else if (tid < 136) {
            int k = tid - 128;
            srcsm[buf * 8 + k] = (c0 + k < sHi) ? srcIdx[b * S_ + c0 + k] : (1 << 29);
        }
    };
    stage(sLo, 0);
    __syncthreads();

    int cur = 0;
    for (int c0 = sLo; c0 < sHi; c0 += ECH) {
        // ---- Phase A: trf[e][w][o] = sum_i x[i,e] * w[o,i,w], all 8 events
        unsigned long long a2[ECH][2];
        #pragma unroll
        for (int e = 0; e < ECH; e++) { a2[e][0] = 0ull; a2[e][1] = 0ull; }

        const float* xb = xs + cur * 128;
        #pragma unroll
        for (int i = 0; i < IC; i++) {
            uint2 hv = wA[i * 256];                        // conflict-free LDS.64
            float2 f01 = __half22float2(*(__half2*)&hv.x);
            float2 f23 = __half22float2(*(__half2*)&hv.y);
            unsigned long long w01 = pack2(f01.x, f01.y);
            unsigned long long w23 = pack2(f23.x, f23.y);
            float4 xv0 = *(const float4*)(xb + i * 8);     // broadcast LDS.128
            float4 xv1 = *(const float4*)(xb + i * 8 + 4);
            unsigned long long xe[ECH];
            xe[0] = pack2(xv0.x, xv0.x);
            xe[1] = pack2(xv0.y, xv0.y);
            xe[2] = pack2(xv0.z, xv0.z);
            xe[3] = pack2(xv0.w, xv0.w);
            xe[4] = pack2(xv1.x, xv1.x);
            xe[5] = pack2(xv1.y, xv1.y);
            xe[6] = pack2(xv1.z, xv1.z);
            xe[7] = pack2(xv1.w, xv1.w);
            #pragma unroll
            for (int e = 0; e < ECH; e++) {
                a2[e][0] = ffma2(w01, xe[e], a2[e][0]);
                a2[e][1] = ffma2(w23, xe[e], a2[e][1]);
            }
        }
        // ---- Store trf fp16, rows (e*64 + w) stride 24 halves, col oA.
        // 16-lane groups hit disjoint bank ranges -> 1 phase per STS.16.
        #pragma unroll
        for (int e = 0; e < ECH; e++) {
            float f0, f1, f2, f3;
            unpack2(a2[e][0], f0, f1);
            unpack2(a2[e][1], f2, f3);
            __half* p = trf + (e * 64 + wqA * 4) * 24 + oA;
            p[0]  = __float2half_rn(f0);
            p[24] = __float2half_rn(f1);
            p[48] = __float2half_rn(f2);
            p[72] = __float2half_rn(f3);
        }
        __syncthreads();   // trf ready; xs[cur] fully consumed

        // ---- Stage next chunk into the other buffer (overlaps Phase B)
        if (c0 + ECH < sHi) stage(c0 + ECH, cur ^ 1);

        // ---- Phase B: overlap-add; 2 conflict-free LDS.128 per event hit
        {
            const int t = t0 + tid;
            const int* sp = srcsm + cur * 8;
            #pragma unroll
            for (int e = 0; e < ECH; e++) {
                int w = t - sp[e];
                if ((unsigned)w < (unsigned)W_) {
                    const __half* rp = trf + (e * 64 + w) * 24;
                    uint4 v0 = *(const uint4*)rp;          // halves o0..o7
                    uint4 v1 = *(const uint4*)(rp + 8);    // halves o8..o15
                    float2 g0 = __half22float2(*(__half2*)&v0.x);
                    float2 g1 = __half22float2(*(__half2*)&v0.y);
                    float2 g2 = __half22float2(*(__half2*)&v0.z);
                    float2 g3 = __half22float2(*(__half2*)&v0.w);
                    float2 g4 = __half22float2(*(__half2*)&v1.x);
                    float2 g5 = __half22float2(*(__half2*)&v1.y);
                    float2 g6 = __half22float2(*(__half2*)&v1.z);
                    float2 g7 = __half22float2(*(__half2*)&v1.w);
                    acc2[0] = add2(acc2[0], pack2(g0.x, g0.y));
                    acc2[1] = add2(acc2[1], pack2(g1.x, g1.y));
                    acc2[2] = add2(acc2[2], pack2(g2.x, g2.y));
                    acc2[3] = add2(acc2[3], pack2(g3.x, g3.y));
                    acc2[4] = add2(acc2[4], pack2(g4.x, g4.y));
                    acc2[5] = add2(acc2[5], pack2(g5.x, g5.y));
                    acc2[6] = add2(acc2[6], pack2(g6.x, g6.y));
                    acc2[7] = add2(acc2[7], pack2(g7.x, g7.y));
                }
            }
        }
        __syncthreads();   // Phase B done reading trf; next x staged
        cur ^= 1;
    }

    // ---- Epilogue: bias + direct coalesced store (lanes = consecutive t)
    {
        const int t = t0 + tid;
        #pragma unroll
        for (int j = 0; j < 8; j++) {
            float f0, f1;
            unpack2(acc2[j], f0, f1);
            int o0 = oBase + 2 * j;
            out[(size_t)(b * O_ + o0) * T + t]     = f0 + __ldg(bias + o0);
            out[(size_t)(b * O_ + o0 + 1) * T + t] = f1 + __ldg(bias + o0 + 1);
        }
    }
}

extern "C" void kernel_launch(void* const* d_in, const int* in_sizes, int n_in,
                              void* d_out, int out_size) {
    (void)in_sizes; (void)n_in;
    const float* x    = (const float*)d_in[0];
    const float* wt   = (const float*)d_in[1];
    const float* bias = (const float*)d_in[2];
    const int*   src  = (const int*)d_in[3];
    float* out = (float*)d_out;

    int T = out_size / (B_ * O_);   // 32768
    cudaFuncSetAttribute(astrf_kernel, cudaFuncAttributeMaxDynamicSharedMemorySize, SMEM_BYTES);
    dim3 grid(T / TT, O_ / OH, B_);
    astrf_kernel<<<grid, 256, SMEM_BYTES>>>(x, wt, bias, src, out, T);
}

// round 14
// speedup vs baseline: 1.4214x; 1.0841x over previous
#include <cuda_runtime.h>
#include <cuda_fp16.h>

// Problem constants
#define B_   4
#define IC   16      // inDim
#define S_   4096    // nSeq
#define O_   64      // outDim
#define W_   64      // nWin
#define OH   16      // outputs per CTA
#define TT   256     // time-tile per CTA
#define ECH  8       // events per chunk

// Shared memory layout (float indices) — identical to the 96.3us kernel
//  wsm : fp16, [row=i*16+wq][o ^ (row&15)][4 halves] -> 256 rows x 128B = 32KB
//  trf : fp32, [e*64+w][20] (o padded 16->20)        -> 512*20*4 = 40KB
//  xs  : fp32, 2 buffers x [i*8 + e] = 2*128 floats
//  src : 2 buffers x 8 ints
#define TRF_OFF_F  8192
#define TRF_FLOATS 10240
#define XS_OFF_F   (TRF_OFF_F + TRF_FLOATS)   // 18432
#define SRC_OFF_F  (XS_OFF_F + 256)           // 18688
#define SMEM_FLOATS (SRC_OFF_F + 16)
#define SMEM_BYTES  (SMEM_FLOATS * 4)         // 74816 B -> 3 CTAs/SM

__device__ __forceinline__ unsigned long long ffma2(unsigned long long a,
                                                    unsigned long long b,
                                                    unsigned long long c) {
    unsigned long long d;
    asm("fma.rn.f32x2 %0, %1, %2, %3;" : "=l"(d) : "l"(a), "l"(b), "l"(c));
    return d;
}
__device__ __forceinline__ unsigned long long add2(unsigned long long a,
                                                   unsigned long long b) {
    unsigned long long d;
    asm("add.rn.f32x2 %0, %1, %2;" : "=l"(d) : "l"(a), "l"(b));
    return d;
}
__device__ __forceinline__ unsigned long long pack2(float lo, float hi) {
    unsigned long long d;
    asm("mov.b64 %0, {%1, %2};" : "=l"(d) : "f"(lo), "f"(hi));
    return d;
}
__device__ __forceinline__ void unpack2(unsigned long long v, float& lo, float& hi) {
    asm("mov.b64 {%0, %1}, %2;" : "=f"(lo), "=f"(hi) : "l"(v));
}

__global__ __launch_bounds__(256, 3)
void astrf_kernel(const float* __restrict__ x, const float* __restrict__ wt,
                  const float* __restrict__ bias, const int* __restrict__ srcIdx,
                  float* __restrict__ out, int T)
{
    extern __shared__ float smem[];
    uint2* wsm2  = (uint2*)smem;                // fp16 weights as half4
    float* trf   = smem + TRF_OFF_F;
    float* xs    = smem + XS_OFF_F;
    int*   srcsm = (int*)(smem + SRC_OFF_F);

    const int tid   = threadIdx.x;
    const int b     = blockIdx.z;
    const int oBase = blockIdx.y * OH;
    const int t0    = blockIdx.x * TT;

    // ---- Stage weights: gmem f32 -> smem f16, XOR-swizzled (coalesced gmem).
    {
        const int lane = tid & 31;
        #pragma unroll
        for (int r = 0; r < 2; r++) {
            const int o = (tid >> 5) + r * 8;     // 0..15
            const float4* gw = (const float4*)(wt + (size_t)(oBase + o) * (IC * W_));
            #pragma unroll
            for (int u = 0; u < 8; u++) {
                int row = lane + u * 32;                   // 0..255 = i*16 + wq
                float4 v = gw[row];
                __half2 h01 = __floats2half2_rn(v.x, v.y);
                __half2 h23 = __floats2half2_rn(v.z, v.w);
                uint2 hv;
                hv.x = *(unsigned*)&h01; hv.y = *(unsigned*)&h23;
                wsm2[row * 16 + (o ^ (row & 15))] = hv;
            }
        }
    }

    // ---- Per-thread binary search for event window [t0-(W-1), t0+TT)
    int sLo, sHi;
    {
        const int* sp = srcIdx + b * S_;
        int lo = 0, hi = S_, tgt = t0 - (W_ - 1);
        while (lo < hi) { int m = (lo + hi) >> 1; if (sp[m] < tgt) lo = m + 1; else hi = m; }
        sLo = lo;
        lo = 0; hi = S_; tgt = t0 + TT;
        while (lo < hi) { int m = (lo + hi) >> 1; if (sp[m] < tgt) lo = m + 1; else hi = m; }
        sHi = lo;
    }

    // Thread roles
    const int oA  = tid & 15;            // Phase A: output lane
    const int wqA = tid >> 4;            // Phase A: w-quad (0..15)

    // Phase-A weight pointer (swizzle term == wqA, constant per thread)
    const uint2* wA = wsm2 + wqA * 16 + (oA ^ wqA);

    // Persistent accumulators: 16 outputs as 8 f32x2
    unsigned long long acc2[8];
    #pragma unroll
    for (int k = 0; k < 8; k++) acc2[k] = 0ull;

    // ---- x/src staging
    auto stage = [&](int c0, int buf) {
        if (tid < 128) {
            int i = tid >> 3, e = tid & 7;
            float v = (c0 + e < sHi) ? x[(size_t)(b * IC + i) * S_ + c0 + e] : 0.f;
            xs[buf * 128 + i * 8 + e] = v;
        } else if (tid < 136) {
            int k = tid - 128;
            srcsm[buf * 8 + k] = (c0 + k < sHi) ? srcIdx[b * S_ + c0 + k] : (1 << 29);
        }
    };
    stage(sLo, 0);
    __syncthreads();

    int cur = 0;
    for (int c0 = sLo; c0 < sHi; c0 += ECH) {
        // ---- Phase A: trf[e][w][o] = sum_i x[i,e] * w[o,i,w]
        // f32x2 lanes pair adjacent EVENTS: a2[k][ep] = (e=2ep, e=2ep+1) at
        // w = wqA*4+k. x pairs load directly from smem (no dup packs).
        unsigned long long a2[4][4];
        #pragma unroll
        for (int k = 0; k < 4; k++)
            #pragma unroll
            for (int ep = 0; ep < 4; ep++) a2[k][ep] = 0ull;

        const float* xb = xs + cur * 128;
        #pragma unroll
        for (int i = 0; i < IC; i++) {
            uint2 hv = wA[i * 256];                        // conflict-free LDS.64
            float2 f01 = __half22float2(*(__half2*)&hv.x);
            float2 f23 = __half22float2(*(__half2*)&hv.y);
            unsigned long long wd0 = pack2(f01.x, f01.x);  // dup w taps
            unsigned long long wd1 = pack2(f01.y, f01.y);
            unsigned long long wd2 = pack2(f23.x, f23.x);
            unsigned long long wd3 = pack2(f23.y, f23.y);
            const ulonglong2* xp = (const ulonglong2*)(xb + i * 8);
            ulonglong2 xq0 = xp[0];                        // (e0,e1),(e2,e3)
            ulonglong2 xq1 = xp[1];                        // (e4,e5),(e6,e7)
            a2[0][0] = ffma2(wd0, xq0.x, a2[0][0]);
            a2[1][0] = ffma2(wd1, xq0.x, a2[1][0]);
            a2[2][0] = ffma2(wd2, xq0.x, a2[2][0]);
            a2[3][0] = ffma2(wd3, xq0.x, a2[3][0]);
            a2[0][1] = ffma2(wd0, xq0.y, a2[0][1]);
            a2[1][1] = ffma2(wd1, xq0.y, a2[1][1]);
            a2[2][1] = ffma2(wd2, xq0.y, a2[2][1]);
            a2[3][1] = ffma2(wd3, xq0.y, a2[3][1]);
            a2[0][2] = ffma2(wd0, xq1.x, a2[0][2]);
            a2[1][2] = ffma2(wd1, xq1.x, a2[1][2]);
            a2[2][2] = ffma2(wd2, xq1.x, a2[2][2]);
            a2[3][2] = ffma2(wd3, xq1.x, a2[3][2]);
            a2[0][3] = ffma2(wd0, xq1.y, a2[0][3]);
            a2[1][3] = ffma2(wd1, xq1.y, a2[1][3]);
            a2[2][3] = ffma2(wd2, xq1.y, a2[2][3]);
            a2[3][3] = ffma2(wd3, xq1.y, a2[3][3]);
        }
        // ---- Store trf fp32, rows (e*64 + w) stride 20, col oA.
        // Same conflict-free 32-bank STS.32 pattern as before.
        #pragma unroll
        for (int ep = 0; ep < 4; ep++) {
            #pragma unroll
            for (int k = 0; k < 4; k++) {
                float fe0, fe1;
                unpack2(a2[k][ep], fe0, fe1);
                float* p0 = trf + ((2 * ep)     * 64 + wqA * 4 + k) * 20 + oA;
                float* p1 = trf + ((2 * ep + 1) * 64 + wqA * 4 + k) * 20 + oA;
                *p0 = fe0;
                *p1 = fe1;
            }
        }
        __syncthreads();   // trf ready; xs[cur] fully consumed

        // ---- Stage next chunk into the other buffer (overlaps Phase B)
        if (c0 + ECH < sHi) stage(c0 + ECH, cur ^ 1);

        // ---- Phase B: overlap-add, 4 LDS.128 per event hit, no atomics
        {
            const int t = t0 + tid;
            const int* sp = srcsm + cur * 8;
            #pragma unroll
            for (int e = 0; e < ECH; e++) {
                int w = t - sp[e];
                if ((unsigned)w < (unsigned)W_) {
                    const ulonglong2* p =
                        (const ulonglong2*)(trf + (e * 64 + w) * 20);
                    #pragma unroll
                    for (int j = 0; j < 4; j++) {
                        ulonglong2 v = p[j];
                        acc2[2*j]   = add2(acc2[2*j],   v.x);
                        acc2[2*j+1] = add2(acc2[2*j+1], v.y);
                    }
                }
            }
        }
        __syncthreads();   // Phase B done reading trf; next x staged
        cur ^= 1;
    }

    // ---- Epilogue: bias + direct coalesced store (lanes = consecutive t)
    {
        const int t = t0 + tid;
        #pragma unroll
        for (int j = 0; j < 8; j++) {
            float f0, f1;
            unpack2(acc2[j], f0, f1);
            int o0 = oBase + 2 * j;
            out[(size_t)(b * O_ + o0) * T + t]     = f0 + __ldg(bias + o0);
            out[(size_t)(b * O_ + o0 + 1) * T + t] = f1 + __ldg(bias + o0 + 1);
        }
    }
}

extern "C" void kernel_launch(void* const* d_in, const int* in_sizes, int n_in,
                              void* d_out, int out_size) {
    (void)in_sizes; (void)n_in;
    const float* x    = (const float*)d_in[0];
    const float* wt   = (const float*)d_in[1];
    const float* bias = (const float*)d_in[2];
    const int*   src  = (const int*)d_in[3];
    float* out = (float*)d_out;

    int T = out_size / (B_ * O_);   // 32768
    cudaFuncSetAttribute(astrf_kernel, cudaFuncAttributeMaxDynamicSharedMemorySize, SMEM_BYTES);
    dim3 grid(T / TT, O_ / OH, B_);
    astrf_kernel<<<grid, 256, SMEM_BYTES>>>(x, wt, bias, src, out, T);
}